// round 4
// baseline (speedup 1.0000x reference)
#include <cuda_runtime.h>
#include <cuda_bf16.h>

#define NBLK 1024
#define NTHR 256
#define NWARP (NTHR / 32)

// Per-block partials + completion ticket (module-scope device memory; no allocs).
__device__ float g_sum[NBLK];
__device__ int   g_cnt[NBLK];
__device__ float g_max[NBLK];
__device__ unsigned int g_done = 0;

__device__ __forceinline__ void point_acc(float x, float y, float z,
                                          float& acc_sum, int& acc_cnt, float& acc_max) {
    // Fold into positive octant: octahedron |x|+|y|+|z| <= 1 is sign-symmetric.
    float qx = fabsf(x), qy = fabsf(y), qz = fabsf(z);
    float s   = qx + qy + qz;
    float x2  = x * x, y2 = y * y, z2 = z * z;
    float dot = fmaf(x, x, fmaf(y, y, z * z));

    const float C = 0.57735026918962576f;           // fp32(1/sqrt(3))
    bool inside = (s * C - C) <= 1e-8f;             // same arithmetic as reference

    float mx  = fmaxf(qx, fmaxf(qy, qz));           // largest |coord|
    float mn  = fminf(qx, fminf(qy, qz));           // smallest
    float mn2 = fminf(x2, fminf(y2, z2));           // mn^2 without an extra mul

    // nearest-vertex distance^2 = dot + 1 - 2*mx
    float d2v = fmaf(-2.0f, mx, dot + 1.0f);

    if (inside) {
        acc_sum += d2v;
        acc_cnt += 1;
    } else {
        // Exact distance^2 to simplex {q>=0, sum=1}: sorted threshold cascade.
        float t1      = s - 1.0f;
        float face_sq = (t1 * (1.0f / 3.0f)) * t1;  // 3*tau3^2
        bool  face_ok = (3.0f * mn >= t1);          // mn >= tau3

        float tau2 = fmaf(0.5f, s - mn, -0.5f);     // (s - mn - 1)/2
        float e    = fmaf(tau2 + tau2, tau2, mn2);  // 2*tau2^2 + mn^2
        bool  edge_ok = fmaf(-2.0f, mx, s + 1.0f) >= mn;  // md >= tau2

        float sq = edge_ok ? e : d2v;               // vertex fallback == d2v (identity)
        sq = face_ok ? face_sq : sq;
        acc_max = fmaxf(acc_max, sq);
    }
}

__global__ void __launch_bounds__(NTHR, 8)
palette_bound_loss_kernel(const float4* __restrict__ pts4,
                          const float*  __restrict__ pts,
                          float* __restrict__ out,
                          int n_items, int n_points) {
    // Staging buffer: 96 float4 per warp (one warp's 32 items x 3 float4).
    __shared__ float4 stage[NWARP * 96];

    float acc_sum = 0.0f;
    int   acc_cnt = 0;
    float acc_max = 0.0f;

    const int lane = threadIdx.x & 31;
    const int wid  = threadIdx.x >> 5;
    const int nthreads = gridDim.x * blockDim.x;
    const int n_f4 = 3 * n_items;                 // total float4s covered by items
    float4* wstage = stage + wid * 96;

    int item       = blockIdx.x * blockDim.x + threadIdx.x;
    int warp_first = item - lane;                 // uniform across the warp

    for (; warp_first < n_items; item += nthreads, warp_first += nthreads) {
        // ---- coalesced load: 3 contiguous LDG.128 per warp (4 lines each) ----
        int qbase = 3 * warp_first;               // first float4 of this warp's chunk
        int q0 = qbase + lane, q1 = q0 + 32, q2 = q0 + 64;
        float4 r0, r1, r2;
        if (q0 < n_f4) r0 = pts4[q0];
        if (q1 < n_f4) r1 = pts4[q1];
        if (q2 < n_f4) r2 = pts4[q2];
        wstage[lane]      = r0;
        wstage[lane + 32] = r1;
        wstage[lane + 64] = r2;
        __syncwarp();

        // ---- read back own item: 3 LDS.128 at 48B stride (conflict-free) ----
        if (item < n_items) {
            float4 f0 = wstage[3 * lane + 0];
            float4 f1 = wstage[3 * lane + 1];
            float4 f2 = wstage[3 * lane + 2];
            point_acc(f0.x, f0.y, f0.z, acc_sum, acc_cnt, acc_max);
            point_acc(f0.w, f1.x, f1.y, acc_sum, acc_cnt, acc_max);
            point_acc(f1.z, f1.w, f2.x, acc_sum, acc_cnt, acc_max);
            point_acc(f2.y, f2.z, f2.w, acc_sum, acc_cnt, acc_max);
        }
        __syncwarp();   // protect stage from next iteration's stores
    }

    // warp reduce: 2 float shuffle trees + hardware redux for the int count
    #pragma unroll
    for (int o = 16; o > 0; o >>= 1) {
        acc_sum += __shfl_down_sync(0xffffffffu, acc_sum, o);
        acc_max  = fmaxf(acc_max, __shfl_down_sync(0xffffffffu, acc_max, o));
    }
    acc_cnt = __reduce_add_sync(0xffffffffu, acc_cnt);

    __shared__ float s_sum[NWARP];
    __shared__ int   s_cnt[NWARP];
    __shared__ float s_max[NWARP];
    if (lane == 0) { s_sum[wid] = acc_sum; s_cnt[wid] = acc_cnt; s_max[wid] = acc_max; }
    __syncthreads();

    __shared__ bool s_is_last;
    if (threadIdx.x == 0) {
        float bs = 0.0f; int bc = 0; float bm = 0.0f;
        #pragma unroll
        for (int i = 0; i < NWARP; i++) {
            bs += s_sum[i]; bc += s_cnt[i]; bm = fmaxf(bm, s_max[i]);
        }
        g_sum[blockIdx.x] = bs;
        g_cnt[blockIdx.x] = bc;
        g_max[blockIdx.x] = bm;
        __threadfence();
        unsigned int ticket = atomicAdd(&g_done, 1u);
        s_is_last = (ticket == (unsigned int)(gridDim.x - 1));
    }
    __syncthreads();

    if (s_is_last) {
        __threadfence();  // acquire side: all blocks' partials visible
        float fs = 0.0f; int fc = 0; float fm = 0.0f;
        for (int i = threadIdx.x; i < NBLK; i += NTHR) {
            fs += g_sum[i]; fc += g_cnt[i]; fm = fmaxf(fm, g_max[i]);
        }
        #pragma unroll
        for (int o = 16; o > 0; o >>= 1) {
            fs += __shfl_down_sync(0xffffffffu, fs, o);
            fm  = fmaxf(fm, __shfl_down_sync(0xffffffffu, fm, o));
        }
        fc = __reduce_add_sync(0xffffffffu, fc);
        if (lane == 0) { s_sum[wid] = fs; s_cnt[wid] = fc; s_max[wid] = fm; }
        __syncthreads();
        if (threadIdx.x == 0) {
            float fs2 = 0.0f; int fc2 = 0; float fm2 = 0.0f;
            #pragma unroll
            for (int i = 0; i < NWARP; i++) {
                fs2 += s_sum[i]; fc2 += s_cnt[i]; fm2 = fmaxf(fm2, s_max[i]);
            }
            // scalar tail (n_points % 4), normally empty for N = 1048576
            for (int p = n_items * 4; p < n_points; p++) {
                point_acc(pts[3 * p + 0], pts[3 * p + 1], pts[3 * p + 2], fs2, fc2, fm2);
            }
            int n_out = n_points - fc2;
            float loss_in  = (fc2   > 0) ? (0.001f * fs2 / (float)fc2) : 0.0f;
            float loss_out = (n_out > 0) ? fm2 : 0.0f;
            out[0] = loss_in + loss_out;
            g_done = 0;  // reset ticket so every graph replay starts clean
        }
    }
}

extern "C" void kernel_launch(void* const* d_in, const int* in_sizes, int n_in,
                              void* d_out, int out_size) {
    const float* pts = (const float*)d_in[0];
    int n_points = in_sizes[0] / 3;
    int n_items  = n_points / 4;   // 4 points (12 floats = 3 float4) per work item
    palette_bound_loss_kernel<<<NBLK, NTHR>>>(
        (const float4*)pts, pts, (float*)d_out, n_items, n_points);
}

// round 5
// speedup vs baseline: 1.0026x; 1.0026x over previous
#include <cuda_runtime.h>
#include <cuda_bf16.h>

#define NBLK  1024
#define NTHR  256
#define NWARP (NTHR / 32)
#define NPART (NBLK * NWARP)   // 8192 per-warp partials

// Per-warp partials (module-scope device memory; no allocs).
__device__ float g_sum[NPART];
__device__ int   g_cnt[NPART];
__device__ float g_max[NPART];

__device__ __forceinline__ void point_acc(float x, float y, float z,
                                          float& acc_sum, int& acc_cnt, float& acc_max) {
    // Fold into positive octant: octahedron |x|+|y|+|z| <= 1 is sign-symmetric.
    float qx = fabsf(x), qy = fabsf(y), qz = fabsf(z);
    float s   = qx + qy + qz;
    float x2  = x * x, y2 = y * y, z2 = z * z;
    float dot = fmaf(x, x, fmaf(y, y, z * z));

    const float C = 0.57735026918962576f;           // fp32(1/sqrt(3))
    bool inside = (s * C - C) <= 1e-8f;             // same arithmetic as reference

    float mx  = fmaxf(qx, fmaxf(qy, qz));           // largest |coord|
    float mn  = fminf(qx, fminf(qy, qz));           // smallest
    float mn2 = fminf(x2, fminf(y2, z2));           // mn^2 without an extra mul

    // nearest-vertex distance^2 = dot + 1 - 2*mx
    float d2v = fmaf(-2.0f, mx, dot + 1.0f);

    if (inside) {
        acc_sum += d2v;
        acc_cnt += 1;
    } else {
        // Exact distance^2 to simplex {q>=0, sum=1}: sorted threshold cascade.
        float t1      = s - 1.0f;
        float face_sq = (t1 * (1.0f / 3.0f)) * t1;  // 3*tau3^2
        bool  face_ok = (3.0f * mn >= t1);          // mn >= tau3

        float tau2 = fmaf(0.5f, s - mn, -0.5f);     // (s - mn - 1)/2
        float e    = fmaf(tau2 + tau2, tau2, mn2);  // 2*tau2^2 + mn^2
        bool  edge_ok = fmaf(-2.0f, mx, s + 1.0f) >= mn;  // md >= tau2

        float sq = edge_ok ? e : d2v;               // vertex fallback == d2v (identity)
        sq = face_ok ? face_sq : sq;
        acc_max = fmaxf(acc_max, sq);
    }
}

// ---- Kernel 1: stream points, one partial per warp, no block sync, no atomics ----
__global__ void __launch_bounds__(NTHR, 8)
pbl_partial_kernel(const float4* __restrict__ pts4, int n_items) {
    float acc_sum = 0.0f;
    int   acc_cnt = 0;
    float acc_max = 0.0f;

    const int nthreads = gridDim.x * blockDim.x;
    for (int item = blockIdx.x * blockDim.x + threadIdx.x; item < n_items; item += nthreads) {
        const float4* g = pts4 + 3 * item;          // 48B-stride float4 loads, MLP=3
        float4 f0 = g[0], f1 = g[1], f2 = g[2];
        point_acc(f0.x, f0.y, f0.z, acc_sum, acc_cnt, acc_max);
        point_acc(f0.w, f1.x, f1.y, acc_sum, acc_cnt, acc_max);
        point_acc(f1.z, f1.w, f2.x, acc_sum, acc_cnt, acc_max);
        point_acc(f2.y, f2.z, f2.w, acc_sum, acc_cnt, acc_max);
    }

    // warp reduce: two interleaved shuffle trees + hardware redux for the count
    #pragma unroll
    for (int o = 16; o > 0; o >>= 1) {
        acc_sum += __shfl_down_sync(0xffffffffu, acc_sum, o);
        acc_max  = fmaxf(acc_max, __shfl_down_sync(0xffffffffu, acc_max, o));
    }
    acc_cnt = __reduce_add_sync(0xffffffffu, acc_cnt);

    if ((threadIdx.x & 31) == 0) {
        int gw = blockIdx.x * NWARP + (threadIdx.x >> 5);
        g_sum[gw] = acc_sum;
        g_cnt[gw] = acc_cnt;
        g_max[gw] = acc_max;
        // kernel-end implicit memory flush makes these visible to kernel 2
    }
}

// ---- Kernel 2: reduce 8192 partials + scalar tail, write the loss ----
__global__ void __launch_bounds__(1024, 1)
pbl_final_kernel(const float* __restrict__ pts, float* __restrict__ out,
                 int n_items, int n_points) {
    float fs = 0.0f; int fc = 0; float fm = 0.0f;
    for (int i = threadIdx.x; i < NPART; i += 1024) {   // 8 independent loads per array
        fs += g_sum[i];
        fc += g_cnt[i];
        fm  = fmaxf(fm, g_max[i]);
    }

    #pragma unroll
    for (int o = 16; o > 0; o >>= 1) {
        fs += __shfl_down_sync(0xffffffffu, fs, o);
        fm  = fmaxf(fm, __shfl_down_sync(0xffffffffu, fm, o));
    }
    fc = __reduce_add_sync(0xffffffffu, fc);

    __shared__ float s_sum[32];
    __shared__ int   s_cnt[32];
    __shared__ float s_max[32];
    int lane = threadIdx.x & 31;
    int wid  = threadIdx.x >> 5;
    if (lane == 0) { s_sum[wid] = fs; s_cnt[wid] = fc; s_max[wid] = fm; }
    __syncthreads();

    if (wid == 0) {
        fs = s_sum[lane]; fc = s_cnt[lane]; fm = s_max[lane];
        #pragma unroll
        for (int o = 16; o > 0; o >>= 1) {
            fs += __shfl_down_sync(0xffffffffu, fs, o);
            fm  = fmaxf(fm, __shfl_down_sync(0xffffffffu, fm, o));
        }
        fc = __reduce_add_sync(0xffffffffu, fc);

        if (lane == 0) {
            // scalar tail (n_points % 4), normally empty for N = 1048576
            for (int p = n_items * 4; p < n_points; p++) {
                point_acc(pts[3 * p + 0], pts[3 * p + 1], pts[3 * p + 2], fs, fc, fm);
            }
            int n_out = n_points - fc;
            float loss_in  = (fc    > 0) ? (0.001f * fs / (float)fc) : 0.0f;
            float loss_out = (n_out > 0) ? fm : 0.0f;
            out[0] = loss_in + loss_out;
        }
    }
}

extern "C" void kernel_launch(void* const* d_in, const int* in_sizes, int n_in,
                              void* d_out, int out_size) {
    const float* pts = (const float*)d_in[0];
    int n_points = in_sizes[0] / 3;
    int n_items  = n_points / 4;   // 4 points (12 floats = 3 float4) per work item
    pbl_partial_kernel<<<NBLK, NTHR>>>((const float4*)pts, n_items);
    pbl_final_kernel<<<1, 1024>>>(pts, (float*)d_out, n_items, n_points);
}

// round 6
// speedup vs baseline: 1.3403x; 1.3368x over previous
#include <cuda_runtime.h>
#include <cuda_bf16.h>
#include <cstdint>

#define NTHR      256
#define IPB       256                 // items per block (1 item = 4 points = 48B)
#define TILE_B    (IPB * 48)          // 12288 bytes per block tile
#define MAXBLK    4096

// Per-block partials (module-scope device memory; no allocs).
__device__ float g_sum[MAXBLK];
__device__ int   g_cnt[MAXBLK];
__device__ float g_max[MAXBLK];

__device__ __forceinline__ void point_acc(float x, float y, float z,
                                          float& acc_sum, int& acc_cnt, float& acc_max) {
    // Fold into positive octant: octahedron |x|+|y|+|z| <= 1 is sign-symmetric.
    float qx = fabsf(x), qy = fabsf(y), qz = fabsf(z);
    float s   = qx + qy + qz;
    float x2  = x * x, y2 = y * y, z2 = z * z;
    float dot = fmaf(x, x, fmaf(y, y, z * z));

    const float C = 0.57735026918962576f;           // fp32(1/sqrt(3))
    bool inside = (s * C - C) <= 1e-8f;             // same arithmetic as reference

    float mx  = fmaxf(qx, fmaxf(qy, qz));
    float mn  = fminf(qx, fminf(qy, qz));
    float mn2 = fminf(x2, fminf(y2, z2));

    float d2v = fmaf(-2.0f, mx, dot + 1.0f);        // nearest-vertex dist^2

    if (inside) {
        acc_sum += d2v;
        acc_cnt += 1;
    } else {
        // Exact distance^2 to simplex {q>=0, sum=1}: sorted threshold cascade.
        float t1      = s - 1.0f;
        float face_sq = (t1 * (1.0f / 3.0f)) * t1;
        bool  face_ok = (3.0f * mn >= t1);

        float tau2 = fmaf(0.5f, s - mn, -0.5f);
        float e    = fmaf(tau2 + tau2, tau2, mn2);
        bool  edge_ok = fmaf(-2.0f, mx, s + 1.0f) >= mn;

        float sq = edge_ok ? e : d2v;
        sq = face_ok ? face_sq : sq;
        acc_max = fmaxf(acc_max, sq);
    }
}

__device__ __forceinline__ uint32_t smem_u32(const void* p) {
    uint32_t a;
    asm("{ .reg .u64 t; cvta.to.shared.u64 t, %1; cvt.u32.u64 %0, t; }" : "=r"(a) : "l"(p));
    return a;
}

// ---- Kernel 1: one 12KB bulk-async (TMA) tile per block, compute from smem ----
__global__ void __launch_bounds__(NTHR)
pbl_partial_kernel(const char* __restrict__ pts_bytes, int n_items) {
    __shared__ alignas(128) float4 tile[TILE_B / 16];   // 768 float4
    __shared__ alignas(8)  uint64_t mbar;
    __shared__ float s_sum[NTHR / 32];
    __shared__ int   s_cnt[NTHR / 32];
    __shared__ float s_max[NTHR / 32];

    const int tid  = threadIdx.x;
    const int lane = tid & 31;
    const int wid  = tid >> 5;

    const int first_item = blockIdx.x * IPB;
    const int blk_items  = min(IPB, n_items - first_item);   // may be <=0 for overshoot blocks
    const uint32_t bytes = (blk_items > 0) ? (uint32_t)blk_items * 48u : 0u;

    const uint32_t mbar_a = smem_u32(&mbar);
    const uint32_t dst_a  = smem_u32(tile);

    if (tid == 0) {
        asm volatile("mbarrier.init.shared.b64 [%0], %1;" :: "r"(mbar_a), "r"(1u) : "memory");
    }
    __syncthreads();

    if (tid == 0) {
        asm volatile("mbarrier.arrive.expect_tx.shared.b64 _, [%0], %1;"
                     :: "r"(mbar_a), "r"(bytes) : "memory");
        if (bytes > 0) {
            const char* src = pts_bytes + (size_t)first_item * 48u;
            asm volatile(
                "cp.async.bulk.shared::cta.global.mbarrier::complete_tx::bytes [%0], [%1], %2, [%3];"
                :: "r"(dst_a), "l"(src), "r"(bytes), "r"(mbar_a) : "memory");
        }
    }

    // wait phase 0 (single use, no loop/flip)
    {
        uint32_t done;
        asm volatile(
            "{\n\t.reg .pred p;\n\t"
            "mbarrier.try_wait.parity.acquire.cta.shared::cta.b64 p, [%1], 0;\n\t"
            "selp.b32 %0, 1, 0, p;\n\t}"
            : "=r"(done) : "r"(mbar_a) : "memory");
        while (!done) {
            asm volatile(
                "{\n\t.reg .pred p;\n\t"
                "mbarrier.try_wait.parity.acquire.cta.shared::cta.b64 p, [%1], 0, 0x989680;\n\t"
                "selp.b32 %0, 1, 0, p;\n\t}"
                : "=r"(done) : "r"(mbar_a) : "memory");
        }
    }

    float acc_sum = 0.0f;
    int   acc_cnt = 0;
    float acc_max = 0.0f;

    if (tid < blk_items) {
        // 3 x LDS.128 at 48B stride — bank-conflict-free (12i mod 32 covers all banks per phase)
        float4 f0 = tile[3 * tid + 0];
        float4 f1 = tile[3 * tid + 1];
        float4 f2 = tile[3 * tid + 2];
        point_acc(f0.x, f0.y, f0.z, acc_sum, acc_cnt, acc_max);
        point_acc(f0.w, f1.x, f1.y, acc_sum, acc_cnt, acc_max);
        point_acc(f1.z, f1.w, f2.x, acc_sum, acc_cnt, acc_max);
        point_acc(f2.y, f2.z, f2.w, acc_sum, acc_cnt, acc_max);
    }

    #pragma unroll
    for (int o = 16; o > 0; o >>= 1) {
        acc_sum += __shfl_down_sync(0xffffffffu, acc_sum, o);
        acc_max  = fmaxf(acc_max, __shfl_down_sync(0xffffffffu, acc_max, o));
    }
    acc_cnt = __reduce_add_sync(0xffffffffu, acc_cnt);

    if (lane == 0) { s_sum[wid] = acc_sum; s_cnt[wid] = acc_cnt; s_max[wid] = acc_max; }
    __syncthreads();

    if (tid == 0) {
        float bs = 0.0f; int bc = 0; float bm = 0.0f;
        #pragma unroll
        for (int i = 0; i < NTHR / 32; i++) {
            bs += s_sum[i]; bc += s_cnt[i]; bm = fmaxf(bm, s_max[i]);
        }
        g_sum[blockIdx.x] = bs;
        g_cnt[blockIdx.x] = bc;
        g_max[blockIdx.x] = bm;
    }
}

// ---- Kernel 2: reduce per-block partials (L2-resident) + scalar tail ----
__global__ void __launch_bounds__(1024, 1)
pbl_final_kernel(const float* __restrict__ pts, float* __restrict__ out,
                 int n_blocks, int n_items, int n_points) {
    float fs = 0.0f; int fc = 0; float fm = 0.0f;
    // n_blocks <= 4096; stride-1024 loop, loads batched by unroll
    #pragma unroll 4
    for (int i = threadIdx.x; i < n_blocks; i += 1024) {
        float a = g_sum[i];
        int   b = g_cnt[i];
        float c = g_max[i];
        fs += a; fc += b; fm = fmaxf(fm, c);
    }

    #pragma unroll
    for (int o = 16; o > 0; o >>= 1) {
        fs += __shfl_down_sync(0xffffffffu, fs, o);
        fm  = fmaxf(fm, __shfl_down_sync(0xffffffffu, fm, o));
    }
    fc = __reduce_add_sync(0xffffffffu, fc);

    __shared__ float s_sum[32];
    __shared__ int   s_cnt[32];
    __shared__ float s_max[32];
    int lane = threadIdx.x & 31;
    int wid  = threadIdx.x >> 5;
    if (lane == 0) { s_sum[wid] = fs; s_cnt[wid] = fc; s_max[wid] = fm; }
    __syncthreads();

    if (wid == 0) {
        fs = s_sum[lane]; fc = s_cnt[lane]; fm = s_max[lane];
        #pragma unroll
        for (int o = 16; o > 0; o >>= 1) {
            fs += __shfl_down_sync(0xffffffffu, fs, o);
            fm  = fmaxf(fm, __shfl_down_sync(0xffffffffu, fm, o));
        }
        fc = __reduce_add_sync(0xffffffffu, fc);

        if (lane == 0) {
            // scalar tail (n_points % 4), normally empty for N = 1048576
            for (int p = n_items * 4; p < n_points; p++) {
                point_acc(pts[3 * p + 0], pts[3 * p + 1], pts[3 * p + 2], fs, fc, fm);
            }
            int n_out = n_points - fc;
            float loss_in  = (fc    > 0) ? (0.001f * fs / (float)fc) : 0.0f;
            float loss_out = (n_out > 0) ? fm : 0.0f;
            out[0] = loss_in + loss_out;
        }
    }
}

extern "C" void kernel_launch(void* const* d_in, const int* in_sizes, int n_in,
                              void* d_out, int out_size) {
    const float* pts = (const float*)d_in[0];
    int n_points = in_sizes[0] / 3;
    int n_items  = n_points / 4;                    // 4 points (48B) per item
    int n_blocks = (n_items + IPB - 1) / IPB;       // 1024 for N = 1048576
    if (n_blocks > MAXBLK) n_blocks = MAXBLK;       // (N fixed; guard only)
    pbl_partial_kernel<<<n_blocks, NTHR>>>((const char*)pts, n_items);
    pbl_final_kernel<<<1, 1024>>>(pts, (float*)d_out, n_blocks, n_items, n_points);
}